// round 16
// baseline (speedup 1.0000x reference)
#include <cuda_runtime.h>
#include <cstdint>

// SimplifiedMambaBlock — analytical identity:
//   h0 = 0 and the scan is purely multiplicative (h = A_t * h, no input
//   injection), so h ≡ 0 → ssm_out ≡ 0 → y ≡ 0 → out = 0; the reference
//   returns residual == x bit-exactly. Optimal kernel = device copy of x.
//
// R15 result: CE+SM concurrent split (50/50) broke the 10.7 µs wall →
// 10.40 µs. Branch timings were unbalanced: SM half finished in 7.33 µs
// (4.57 TB/s under contention), CE half was the ~10.4 µs critical path
// (3.22 TB/s). R16: rebalance the split so both clients finish together:
// SM share s solving s/4.57 = (1-s)/3.22 → s ≈ 0.59. Predicted 8.6 µs if
// per-client rates hold, ~10.2 µs if the LTS cap is globally
// work-conserving. All failure paths degrade to single memcpy (10.7 µs).

__global__ void __launch_bounds__(256)
copy_vec4(const float4* __restrict__ src, float4* __restrict__ dst,
          unsigned n_vec4)
{
    unsigned i = blockIdx.x * 256u + threadIdx.x;
    unsigned stride = gridDim.x * 256u;
    for (; i < n_vec4; i += stride) dst[i] = src[i];
}

// Lazily created on first kernel_launch call (after harness context init,
// before graph capture — the harness runs one correctness call first).
// Host-side context resources only; no device-buffer allocation.
static cudaStream_t g_s2   = nullptr;
static cudaEvent_t  g_fork = nullptr;
static cudaEvent_t  g_join = nullptr;
static int g_init_state = 0;   // 0 = not tried, 1 = ok, -1 = failed

static bool ensure_init()
{
    if (g_init_state != 0) return g_init_state == 1;

    cudaStreamCaptureStatus st = cudaStreamCaptureStatusNone;
    if (cudaStreamIsCapturing(0, &st) == cudaSuccess &&
        st != cudaStreamCaptureStatusNone) {
        return false;           // never create resources mid-capture; retry later
    }

    if (cudaStreamCreateWithFlags(&g_s2, cudaStreamNonBlocking) == cudaSuccess &&
        cudaEventCreateWithFlags(&g_fork, cudaEventDisableTiming) == cudaSuccess &&
        cudaEventCreateWithFlags(&g_join, cudaEventDisableTiming) == cudaSuccess) {
        g_init_state = 1;
        return true;
    }
    g_init_state = -1;
    return false;
}

extern "C" void kernel_launch(void* const* d_in, const int* in_sizes, int n_in,
                              void* d_out, int out_size)
{
    const char* x = (const char*)d_in[0];     // metadata order: x first (fp32)
    char* out     = (char*)d_out;
    size_t bytes  = (size_t)out_size * sizeof(float);   // 33.55 MB

    bool forked = false;
    if (ensure_init()) {
        if (cudaEventRecord(g_fork, 0) == cudaSuccess &&
            cudaStreamWaitEvent(g_s2, g_fork, 0) == cudaSuccess) {
            forked = true;
        }
    }

    if (!forked) {
        cudaMemcpyAsync(out, x, bytes, cudaMemcpyDeviceToDevice, 0);
        return;
    }

    // Rebalanced split: SM gets ~59% (high range), CE ~41% (low range).
    // Split point on a 128B boundary.
    size_t ce_bytes = (size_t)((double)bytes * 0.41) & ~(size_t)127;
    size_t sm_bytes = bytes - ce_bytes;

    // Client 1: copy engine — low 41%, on the capture stream.
    cudaMemcpyAsync(out, x, ce_bytes, cudaMemcpyDeviceToDevice, 0);

    // Client 2: SM kernel — high 59%, on the forked stream.
    unsigned n_vec4 = (unsigned)(sm_bytes >> 4);          // 16B multiple
    copy_vec4<<<2048, 256, 0, g_s2>>>(
        (const float4*)(x + ce_bytes), (float4*)(out + ce_bytes), n_vec4);

    // Join the side stream back into the capture stream.
    cudaEventRecord(g_join, g_s2);
    cudaStreamWaitEvent(0, g_join, 0);
}